// round 17
// baseline (speedup 1.0000x reference)
#include <cuda_runtime.h>
#include <cstdint>

// LIF neuron scan: x[B=64, S=1024, F=512] fp32 -> spikes (0/1) fp32.
// m = 0.95*m + x_t ; s = (m > 0.5) ; m = s ? 0 : m
// RESOLVED MODEL: the 63-67% "DRAM plateau" was an artifact — in-window the
// kernel streams 268MB through LTS at 6.4-6.75 TB/s, i.e. 93-98% of the
// ~6300 B/cyc LTS chip cap. L2 replay-residue hides ~50MB from the DRAM
// counter. Floor ~= 39us in-window. R16 (NSTAGE=3) lost ~2us of in-window
// depth vs R5; this round restores R5's 32KB/block steady in-flight within
// 48KB STATIC smem: CH=16, NSTAGE=6 (8KB stages). Stores stay write-through
// (__stwt cut the harness-vs-ncu gap 10us -> 6.6us).

#define LIF_B 64
#define LIF_S 1024
#define LIF_F 512
#define LIF_CH 16                       // time steps per stage (fine-grained)
#define LIF_NSTAGE 6                    // 6 x 8KB = 48KB static ring
#define LIF_THREADS 128
#define LIF_STAGE_FLOATS (LIF_CH * LIF_THREADS)   // 2048 floats = 8KB/stage

__device__ __forceinline__ void cp_async16(uint32_t dst, const float* src) {
    asm volatile("cp.async.cg.shared.global [%0], [%1], 16;\n"
                 :: "r"(dst), "l"(src));
}
__device__ __forceinline__ void cp_commit() {
    asm volatile("cp.async.commit_group;\n" ::: "memory");
}
template <int N>
__device__ __forceinline__ void cp_wait() {
    asm volatile("cp.async.wait_group %0;\n" :: "n"(N) : "memory");
}

// Fill stage `st` with time steps [t0, t0+16). Warp w covers rows k*4+w,
// lane = 16B chunk of the 512B row -> coalesced, 4 cp.async per thread.
__device__ __forceinline__ void lif_fill(uint32_t sm_base, const float* __restrict__ xb,
                                         int st, int t0, int w, int lane) {
    const uint32_t sdst = sm_base + (uint32_t)(st * LIF_STAGE_FLOATS) * 4u;
    #pragma unroll
    for (int k = 0; k < 4; k++) {
        const int c = k * 4 + w;  // step within stage, warp-uniform
        cp_async16(sdst + (uint32_t)(c * LIF_THREADS + lane * 4) * 4u,
                   xb + (size_t)(t0 + c) * LIF_F + lane * 4);
    }
}

__global__ __launch_bounds__(LIF_THREADS)
void lif_scan_kernel(const float* __restrict__ x, float* __restrict__ out) {
    __shared__ float sm[LIF_NSTAGE * LIF_STAGE_FLOATS];   // 48KB static
    const int tid = threadIdx.x;
    const int w = tid >> 5;
    const int lane = tid & 31;

    // Block covers 128 consecutive chains (same b; f0..f0+127): 512B/step rows.
    const int chain0 = blockIdx.x * LIF_THREADS;
    const int b = chain0 >> 9;           // / 512
    const int f0 = chain0 & (LIF_F - 1); // % 512
    const float* xb = x + (size_t)b * LIF_S * LIF_F + f0;
    float* op = out + (size_t)b * LIF_S * LIF_F + f0 + tid;  // this thread's column

    const uint32_t sm_base = (uint32_t)__cvta_generic_to_shared(sm);

    // Prologue: stages 0..4 issued (5 groups).
    #pragma unroll
    for (int s = 0; s < LIF_NSTAGE - 1; s++) {
        lif_fill(sm_base, xb, s, s * LIF_CH, w, lane);
        cp_commit();
    }

    float m = 0.0f;
    const int NIT = LIF_S / LIF_CH;  // 64 stages total

    #pragma unroll 1
    for (int s = 0; s < NIT; s++) {
        // Issue next fill; steady state keeps 4 stages (32KB) in flight.
        if (s + LIF_NSTAGE - 1 < NIT)
            lif_fill(sm_base, xb, (s + LIF_NSTAGE - 1) % LIF_NSTAGE,
                     (s + LIF_NSTAGE - 1) * LIF_CH, w, lane);
        cp_commit();                 // one group per iteration (empty ok at tail)
        cp_wait<LIF_NSTAGE - 2>();   // stage s complete
        __syncthreads();             // smem written by other warps

        const float* stage = sm + (s % LIF_NSTAGE) * LIF_STAGE_FLOATS;

        float xv[LIF_CH];
        #pragma unroll
        for (int c = 0; c < LIF_CH; c++)
            xv[c] = stage[c * LIF_THREADS + tid];   // conflict-free LDS

        float sv[LIF_CH];
        #pragma unroll
        for (int c = 0; c < LIF_CH; c++) {
            m = fmaf(0.95f, m, xv[c]);
            const bool fire = (m > 0.5f);
            sv[c] = fire ? 1.0f : 0.0f;
            m = fire ? 0.0f : m;
        }

        float* o = op + (size_t)s * LIF_CH * LIF_F;
        #pragma unroll
        for (int c = 0; c < LIF_CH; c++)
            __stwt(o + (size_t)c * LIF_F, sv[c]);   // write-through: no dirty L2

        __syncthreads();  // all reads done before this buffer is refilled
    }
}

extern "C" void kernel_launch(void* const* d_in, const int* in_sizes, int n_in,
                              void* d_out, int out_size) {
    (void)in_sizes; (void)n_in; (void)out_size;
    const float* x = (const float*)d_in[0];
    float* out = (float*)d_out;
    const int blocks = (LIF_B * LIF_F) / LIF_THREADS;  // 256
    lif_scan_kernel<<<blocks, LIF_THREADS>>>(x, out);
}